// round 8
// baseline (speedup 1.0000x reference)
#include <cuda_runtime.h>
#include <math.h>

#define BB 16
#define SS 512
#define HH 1024
#define KSLOT 32
#define EE 1024
#define MROWS (BB * KSLOT)   // 512

// ---------------- scratch ----------------
__device__ float g_naf[BB * HH];
__device__ float g_ch [BB * HH];
__device__ float g_Xhi[MROWS * HH];
__device__ float g_Xlo[MROWS * HH];
__device__ float g_Whi[3 * HH * HH];   // z: 0=node_dense, 1=Wa(=W0+W2), 2=Wb(=W1-W2)
__device__ float g_Wlo[3 * HH * HH];
__device__ float g_A  [MROWS * HH];
__device__ float g_Bm [MROWS * HH];
__device__ float g_Hn [MROWS * HH];
__device__ int   g_m  [BB];

__device__ __forceinline__ float tanh_fast(float x) {
    float r;
    asm("tanh.approx.f32 %0, %1;" : "=f"(r) : "f"(x));
    return r;
}
__device__ __forceinline__ float tf32_hi(float x) {
    unsigned u;
    asm("cvt.rna.tf32.f32 %0, %1;" : "=r"(u) : "f"(x));
    return __uint_as_float(u);
}
__device__ __forceinline__ void split2(float x, float& hi, float& lo) {
    hi = tf32_hi(x);
    lo = tf32_hi(x - hi);
}

// ---------------- 1) fused: fold+split weights, cls token heads ----------------
__global__ void prep_fused(const float* __restrict__ eW, const float* __restrict__ ndW,
                           const float* __restrict__ seq,
                           const float* __restrict__ nafW, const float* __restrict__ nafb,
                           const float* __restrict__ cdW,  const float* __restrict__ cdb) {
    __shared__ float s_x[HH];
    int blk = blockIdx.x;
    int tid = threadIdx.x;
    if (blk < 4096) {
        int idx = blk * 256 + tid;
        float w0 = eW[idx];
        float w1 = eW[HH * HH + idx];
        float w2 = eW[2 * HH * HH + idx];
        float nd = ndW[idx];
        float h, l;
        split2(nd,      h, l); g_Whi[idx] = h;                g_Wlo[idx] = l;
        split2(w0 + w2, h, l); g_Whi[HH * HH + idx] = h;      g_Wlo[HH * HH + idx] = l;
        split2(w1 - w2, h, l); g_Whi[2 * HH * HH + idx] = h;  g_Wlo[2 * HH * HH + idx] = l;
    } else {
        int blkc = blk - 4096;
        int b = blkc >> 2;
        int c = (blkc & 3) * 256 + tid;
        for (int h = tid; h < HH; h += 256) s_x[h] = seq[(size_t)b * SS * HH + h];
        __syncthreads();
        float an = 0.f, ac = 0.f;
        for (int k = 0; k < HH; k++) {
            float x = s_x[k];
            an = fmaf(x, nafW[(size_t)k * HH + c], an);
            ac = fmaf(x, cdW [(size_t)k * HH + c], ac);
        }
        g_naf[b * HH + c] = an + nafb[c];
        g_ch [b * HH + c] = tanhf(ac + cdb[c]);
    }
}

// ---------------- 2) segment means -> full_nodes (tf32-split, fused) ----------------
__global__ void nodes_kernel(const float* __restrict__ seq, const int* __restrict__ off) {
    int b = blockIdx.x, k = blockIdx.y, tid = threadIdx.x;
    const int* po = off + b * KSLOT;
    int n = 0;
    #pragma unroll
    for (int t = 1; t < KSLOT; t++) n += (po[t] > 0);
    size_t base = ((size_t)(b * KSLOT + k)) * HH;
    if (k < n) {
        int start = (k == 0) ? 1 : po[k] + 1;
        int end   = po[k + 1];
        float inv = 1.0f / (float)(end - start + 1);
        for (int h = tid; h < HH; h += 128) {
            float acc = 0.f;
            for (int r = start; r <= end; r++) acc += seq[((size_t)b * SS + r) * HH + h];
            float hi, lo;
            split2(acc * inv, hi, lo);
            g_Xhi[base + h] = hi;
            g_Xlo[base + h] = lo;
        }
    } else if (k == n) {
        for (int h = tid; h < HH; h += 128) {
            float hi, lo;
            split2(g_naf[b * HH + h], hi, lo);
            g_Xhi[base + h] = hi;
            g_Xlo[base + h] = lo;
        }
    } else {
        for (int h = tid; h < HH; h += 128) {
            g_Xhi[base + h] = 0.f;
            g_Xlo[base + h] = 0.f;
        }
    }
    if (k == 0 && tid == 0) g_m[b] = n + 1;
}

// ---------------- 3) tensor-core GEMM (3xTF32), fragment-major smem ----------------
// C[512,1024] = X @ W[z], z in {0,1,2}. BM=64, BN=64, BK=32, 128 thr (2x2 warps).
// smem holds tiles pre-permuted into MMA fragment order:
//   fA[ks][mb][lane][slot] (4x4x32x4 floats): slot = half + 2*quad, lane = g*4+tg
//   fB[ks][nb][lane][slot] (4x8x32x2 floats): slot = quad,          lane = g*4+tg
__device__ __forceinline__ void mma8(float* c, const unsigned* a, const unsigned* b) {
    asm volatile(
        "mma.sync.aligned.m16n8k8.row.col.f32.tf32.tf32.f32 "
        "{%0,%1,%2,%3}, {%4,%5,%6,%7}, {%8,%9}, {%0,%1,%2,%3};"
        : "+f"(c[0]), "+f"(c[1]), "+f"(c[2]), "+f"(c[3])
        : "r"(a[0]), "r"(a[1]), "r"(a[2]), "r"(a[3]), "r"(b[0]), "r"(b[1]));
}

__global__ __launch_bounds__(128) void mma_gemm(const float* __restrict__ ndb) {
    __shared__ __align__(16) float fAh[2048];
    __shared__ __align__(16) float fAl[2048];
    __shared__ __align__(16) float fBh[2048];
    __shared__ __align__(16) float fBl[2048];

    int z = blockIdx.z;
    float* Cp = (z == 0) ? g_Hn : (z == 1) ? g_A : g_Bm;
    const float* Whz = g_Whi + (size_t)z * HH * HH;
    const float* Wlz = g_Wlo + (size_t)z * HH * HH;

    int bm = blockIdx.x * 64, bn = blockIdx.y * 64;
    int tid = threadIdx.x;
    int warp = tid >> 5, lane = tid & 31;
    int warpM = warp >> 1, warpN = warp & 1;
    int g = lane >> 2, tg = lane & 3;

    float acc[2][4][4];
    #pragma unroll
    for (int mt = 0; mt < 2; mt++)
        #pragma unroll
        for (int nt = 0; nt < 4; nt++)
            #pragma unroll
            for (int r = 0; r < 4; r++) acc[mt][nt][r] = 0.f;

    for (int kt = 0; kt < HH / 32; kt++) {
        int k0 = kt * 32;
        // ---- A tile (64 rows x 32 k), hi+lo -> fragment-major scatter ----
        #pragma unroll
        for (int it = 0; it < 4; it++) {
            int idx = it * 128 + tid;
            int row = idx >> 3, k4 = idx & 7;       // k4: float4 index in 32-k
            int kk8 = k4 >> 1, quad = k4 & 1;
            int mb = row >> 4, rl = row & 15;
            int half = rl >> 3, gg = rl & 7;
            const float* ph = &g_Xhi[(size_t)(bm + row) * HH + k0 + k4 * 4];
            const float* pl = &g_Xlo[(size_t)(bm + row) * HH + k0 + k4 * 4];
            float4 vh = *(const float4*)ph;
            float4 vl = *(const float4*)pl;
            int a0 = ((kk8 * 4 + mb) * 32 + gg * 4) * 4 + half + 2 * quad;
            fAh[a0]      = vh.x; fAh[a0 + 4]  = vh.y;
            fAh[a0 + 8]  = vh.z; fAh[a0 + 12] = vh.w;
            fAl[a0]      = vl.x; fAl[a0 + 4]  = vl.y;
            fAl[a0 + 8]  = vl.z; fAl[a0 + 12] = vl.w;
        }
        // ---- B tile (32 k x 64 n), hi+lo -> fragment-major scatter ----
        #pragma unroll
        for (int it = 0; it < 4; it++) {
            int idx = it * 128 + tid;
            int kr = idx >> 4, n4 = idx & 15;       // n4: float4 index in 64-n
            int kk8 = kr >> 3, kl = kr & 7;
            int quad = kl >> 2, tgB = kl & 3;
            int nb = n4 >> 1;
            int gB0 = (n4 & 1) * 4;                 // first of 4 consecutive g's
            float4 vh = *(const float4*)&Whz[(size_t)(k0 + kr) * HH + bn + n4 * 4];
            float4 vl = *(const float4*)&Wlz[(size_t)(k0 + kr) * HH + bn + n4 * 4];
            int b0 = ((kk8 * 8 + nb) * 32 + gB0 * 4 + tgB) * 2 + quad;
            fBh[b0]      = vh.x; fBh[b0 + 8]  = vh.y;
            fBh[b0 + 16] = vh.z; fBh[b0 + 24] = vh.w;
            fBl[b0]      = vl.x; fBl[b0 + 8]  = vl.y;
            fBl[b0 + 16] = vl.z; fBl[b0 + 24] = vl.w;
        }
        __syncthreads();

        #pragma unroll
        for (int ks = 0; ks < 4; ks++) {
            float4 fah[2], fal[2];
            float2 fbh[4], fbl[4];
            #pragma unroll
            for (int mt = 0; mt < 2; mt++) {
                int mb = warpM * 2 + mt;
                fah[mt] = *(const float4*)&fAh[((ks * 4 + mb) * 32 + lane) * 4];
                fal[mt] = *(const float4*)&fAl[((ks * 4 + mb) * 32 + lane) * 4];
            }
            #pragma unroll
            for (int nt = 0; nt < 4; nt++) {
                int nb = warpN * 4 + nt;
                fbh[nt] = *(const float2*)&fBh[((ks * 8 + nb) * 32 + lane) * 2];
                fbl[nt] = *(const float2*)&fBl[((ks * 8 + nb) * 32 + lane) * 2];
            }
            #pragma unroll
            for (int mt = 0; mt < 2; mt++)
                #pragma unroll
                for (int nt = 0; nt < 4; nt++) {
                    mma8(acc[mt][nt], (const unsigned*)&fah[mt], (const unsigned*)&fbh[nt]);
                    mma8(acc[mt][nt], (const unsigned*)&fal[mt], (const unsigned*)&fbh[nt]);
                    mma8(acc[mt][nt], (const unsigned*)&fah[mt], (const unsigned*)&fbl[nt]);
                }
        }
        __syncthreads();
    }

    // epilogue
    #pragma unroll
    for (int mt = 0; mt < 2; mt++) {
        #pragma unroll
        for (int half = 0; half < 2; half++) {
            int m = bm + warpM * 32 + mt * 16 + g + half * 8;
            #pragma unroll
            for (int nt = 0; nt < 4; nt++) {
                int n = bn + warpN * 32 + nt * 8 + tg * 2;
                float v0 = acc[mt][nt][half * 2];
                float v1 = acc[mt][nt][half * 2 + 1];
                if (z == 0) {
                    v0 = tanhf(v0 + ndb[n]);
                    v1 = tanhf(v1 + ndb[n + 1]);
                }
                *(float2*)&Cp[(size_t)m * HH + n] = make_float2(v0, v1);
            }
        }
    }
}

// ---------------- 4) tail: node+cls logits, then edges ----------------
__global__ __launch_bounds__(256) void tail_kernel(
        const float* __restrict__ noW, const float* __restrict__ nob,
        const float* __restrict__ coW, const float* __restrict__ cob,
        const float* __restrict__ eb,
        const float* __restrict__ eoW, const float* __restrict__ eob,
        float* __restrict__ out) {
    __shared__ __align__(16) float s_B[HH];
    __shared__ __align__(16) float s_eb[HH];
    __shared__ __align__(16) float s_w0[HH];
    __shared__ __align__(16) float s_w1[HH];
    __shared__ float sred[16];
    int blk = blockIdx.x;
    int tid = threadIdx.x;
    int lane = tid & 31, wid = tid >> 5;

    if (blk < 528) {
        const float* src;
        const float* Wv;
        const float* bv;
        float* dst;
        if (blk < MROWS) {
            src = g_Hn + (size_t)blk * HH; Wv = noW; bv = nob; dst = out + 32 + blk * 2;
        } else {
            int b = blk - MROWS;
            src = g_ch + (size_t)b * HH;  Wv = coW; bv = cob; dst = out + b * 2;
        }
        float p0 = 0.f, p1 = 0.f;
        for (int h = tid; h < HH; h += 256) {
            float v = src[h];
            p0 = fmaf(v, Wv[h * 2],     p0);
            p1 = fmaf(v, Wv[h * 2 + 1], p1);
        }
        #pragma unroll
        for (int o = 16; o > 0; o >>= 1) {
            p0 += __shfl_down_sync(0xffffffffu, p0, o);
            p1 += __shfl_down_sync(0xffffffffu, p1, o);
        }
        if (lane == 0) { sred[wid * 2] = p0; sred[wid * 2 + 1] = p1; }
        __syncthreads();
        if (tid == 0) {
            float a0 = 0.f, a1 = 0.f;
            for (int w = 0; w < 8; w++) { a0 += sred[w * 2]; a1 += sred[w * 2 + 1]; }
            dst[0] = a0 + bv[0]; dst[1] = a1 + bv[1];
        }
        return;
    }

    int eidx = blk - 528;
    int b = eidx / (KSLOT + 1);
    int i = eidx - b * (KSLOT + 1);
    int m = g_m[b];
    float* outp = out + 32 + MROWS * 2;

    for (int h = tid; h < HH; h += 256) {
        s_eb[h] = eb[h];
        s_w0[h] = eoW[h * 2];
        s_w1[h] = eoW[h * 2 + 1];
    }
    if (i < KSLOT && i < m) {
        for (int h = tid; h < HH; h += 256)
            s_B[h] = g_Bm[((size_t)(b * KSLOT + i)) * HH + h];
    }
    __syncthreads();

    if (i < KSLOT) {
        if (i >= m) return;
        for (int j = wid; j < m; j += 8) {
            const float4* Aj = (const float4*)(g_A + ((size_t)(b * KSLOT + j)) * HH);
            float p0 = 0.f, p1 = 0.f;
            #pragma unroll
            for (int it = 0; it < 8; it++) {
                int h4 = it * 32 + lane;
                float4 a  = Aj[h4];
                float4 bv = *(const float4*)&s_B[h4 * 4];
                float4 ev = *(const float4*)&s_eb[h4 * 4];
                float4 w0 = *(const float4*)&s_w0[h4 * 4];
                float4 w1 = *(const float4*)&s_w1[h4 * 4];
                float v0 = tanh_fast(a.x + bv.x + ev.x);
                float v1 = tanh_fast(a.y + bv.y + ev.y);
                float v2 = tanh_fast(a.z + bv.z + ev.z);
                float v3 = tanh_fast(a.w + bv.w + ev.w);
                p0 = fmaf(v0, w0.x, fmaf(v1, w0.y, fmaf(v2, w0.z, fmaf(v3, w0.w, p0))));
                p1 = fmaf(v0, w1.x, fmaf(v1, w1.y, fmaf(v2, w1.z, fmaf(v3, w1.w, p1))));
            }
            #pragma unroll
            for (int o = 16; o > 0; o >>= 1) {
                p0 += __shfl_down_sync(0xffffffffu, p0, o);
                p1 += __shfl_down_sync(0xffffffffu, p1, o);
            }
            if (lane == 0) {
                int e = i * m + j;
                outp[((size_t)b * EE + e) * 2]     = p0 + eob[0];
                outp[((size_t)b * EE + e) * 2 + 1] = p1 + eob[1];
            }
        }
    } else {
        float p0 = 0.f, p1 = 0.f;
        for (int h = tid; h < HH; h += 256) {
            float v = tanhf(s_eb[h]);
            p0 = fmaf(v, s_w0[h], p0);
            p1 = fmaf(v, s_w1[h], p1);
        }
        #pragma unroll
        for (int o = 16; o > 0; o >>= 1) {
            p0 += __shfl_down_sync(0xffffffffu, p0, o);
            p1 += __shfl_down_sync(0xffffffffu, p1, o);
        }
        if (lane == 0) { sred[wid * 2] = p0; sred[wid * 2 + 1] = p1; }
        __syncthreads();
        if (tid == 0) {
            float a0 = 0.f, a1 = 0.f;
            for (int w = 0; w < 8; w++) { a0 += sred[w * 2]; a1 += sred[w * 2 + 1]; }
            sred[0] = a0 + eob[0]; sred[1] = a1 + eob[1];
        }
        __syncthreads();
        float c0 = sred[0], c1 = sred[1];
        for (int e = m * m + tid; e < EE; e += 256) {
            outp[((size_t)b * EE + e) * 2]     = c0;
            outp[((size_t)b * EE + e) * 2 + 1] = c1;
        }
    }
}

// ---------------- launch ----------------
extern "C" void kernel_launch(void* const* d_in, const int* in_sizes, int n_in,
                              void* d_out, int out_size) {
    const float* seq  = (const float*)d_in[0];
    const int*   off  = (const int*)  d_in[1];
    const float* nafW = (const float*)d_in[2];
    const float* nafb = (const float*)d_in[3];
    const float* cdW  = (const float*)d_in[4];
    const float* cdb  = (const float*)d_in[5];
    const float* coW  = (const float*)d_in[6];
    const float* cob  = (const float*)d_in[7];
    const float* ndW  = (const float*)d_in[8];
    const float* ndb  = (const float*)d_in[9];
    const float* noW  = (const float*)d_in[10];
    const float* nob  = (const float*)d_in[11];
    const float* edW  = (const float*)d_in[12];
    const float* edb  = (const float*)d_in[13];
    const float* eoW  = (const float*)d_in[14];
    const float* eob  = (const float*)d_in[15];
    float* out = (float*)d_out;

    prep_fused<<<4160, 256>>>(edW, ndW, seq, nafW, nafb, cdW, cdb);
    nodes_kernel<<<dim3(BB, KSLOT), 128>>>(seq, off);
    mma_gemm<<<dim3(512 / 64, HH / 64, 3), 128>>>(ndb);
    tail_kernel<<<528 + BB * (KSLOT + 1), 256>>>(noW, nob, coW, cob, edb, eoW, eob, out);
}

// round 16
// speedup vs baseline: 1.4425x; 1.4425x over previous
#include <cuda_runtime.h>
#include <math.h>

#define BB 16
#define SS 512
#define HH 1024
#define KSLOT 32
#define EE 1024
#define MROWS (BB * KSLOT)   // 512

// ---------------- scratch ----------------
__device__ float g_naf[BB * HH];
__device__ float g_ch [BB * HH];
__device__ float g_Xhi[MROWS * HH];
__device__ float g_Xlo[MROWS * HH];
__device__ float g_Whi[3 * HH * HH];   // z: 0=node_dense, 1=Wa(=W0+W2), 2=Wb(=W1-W2)
__device__ float g_Wlo[3 * HH * HH];
__device__ float g_A  [MROWS * HH];
__device__ float g_Bm [MROWS * HH];
__device__ float g_Hn [MROWS * HH];
__device__ int   g_m  [BB];

__device__ __forceinline__ float tanh_fast(float x) {
    float r;
    asm("tanh.approx.f32 %0, %1;" : "=f"(r) : "f"(x));
    return r;
}
__device__ __forceinline__ float tf32_hi(float x) {
    unsigned u;
    asm("cvt.rna.tf32.f32 %0, %1;" : "=r"(u) : "f"(x));
    return __uint_as_float(u);
}
__device__ __forceinline__ void split2(float x, float& hi, float& lo) {
    hi = tf32_hi(x);
    lo = tf32_hi(x - hi);
}

// ---------------- 1) fused: fold+split weights, cls token heads ----------------
__global__ void prep_fused(const float* __restrict__ eW, const float* __restrict__ ndW,
                           const float* __restrict__ seq,
                           const float* __restrict__ nafW, const float* __restrict__ nafb,
                           const float* __restrict__ cdW,  const float* __restrict__ cdb) {
    __shared__ float s_x[HH];
    int blk = blockIdx.x;
    int tid = threadIdx.x;
    if (blk < 4096) {
        int idx = blk * 256 + tid;
        float w0 = eW[idx];
        float w1 = eW[HH * HH + idx];
        float w2 = eW[2 * HH * HH + idx];
        float nd = ndW[idx];
        float h, l;
        split2(nd,      h, l); g_Whi[idx] = h;                g_Wlo[idx] = l;
        split2(w0 + w2, h, l); g_Whi[HH * HH + idx] = h;      g_Wlo[HH * HH + idx] = l;
        split2(w1 - w2, h, l); g_Whi[2 * HH * HH + idx] = h;  g_Wlo[2 * HH * HH + idx] = l;
    } else {
        int blkc = blk - 4096;
        int b = blkc >> 2;
        int c = (blkc & 3) * 256 + tid;
        for (int h = tid; h < HH; h += 256) s_x[h] = seq[(size_t)b * SS * HH + h];
        __syncthreads();
        float an = 0.f, ac = 0.f;
        for (int k = 0; k < HH; k++) {
            float x = s_x[k];
            an = fmaf(x, nafW[(size_t)k * HH + c], an);
            ac = fmaf(x, cdW [(size_t)k * HH + c], ac);
        }
        g_naf[b * HH + c] = an + nafb[c];
        g_ch [b * HH + c] = tanhf(ac + cdb[c]);
    }
}

// ---------------- 2) segment means -> full_nodes (tf32-split, fused) ----------------
__global__ void nodes_kernel(const float* __restrict__ seq, const int* __restrict__ off) {
    int b = blockIdx.x, k = blockIdx.y, tid = threadIdx.x;
    const int* po = off + b * KSLOT;
    int n = 0;
    #pragma unroll
    for (int t = 1; t < KSLOT; t++) n += (po[t] > 0);
    size_t base = ((size_t)(b * KSLOT + k)) * HH;
    if (k < n) {
        int start = (k == 0) ? 1 : po[k] + 1;
        int end   = po[k + 1];
        float inv = 1.0f / (float)(end - start + 1);
        for (int h = tid; h < HH; h += 128) {
            float acc = 0.f;
            for (int r = start; r <= end; r++) acc += seq[((size_t)b * SS + r) * HH + h];
            float hi, lo;
            split2(acc * inv, hi, lo);
            g_Xhi[base + h] = hi;
            g_Xlo[base + h] = lo;
        }
    } else if (k == n) {
        for (int h = tid; h < HH; h += 128) {
            float hi, lo;
            split2(g_naf[b * HH + h], hi, lo);
            g_Xhi[base + h] = hi;
            g_Xlo[base + h] = lo;
        }
    } else {
        for (int h = tid; h < HH; h += 128) {
            g_Xhi[base + h] = 0.f;
            g_Xlo[base + h] = 0.f;
        }
    }
    if (k == 0 && tid == 0) g_m[b] = n + 1;
}

// ---------------- 3) tensor-core GEMM (3xTF32), in-CTA split-K ----------------
// C[512,1024] = X @ W[z]. BM=64, BN=64, BK=32. 256 threads = 2 warpgroups;
// warpgroup wg handles k-tiles kt = wg, wg+2, ... each with its own smem set.
// Final combine: wg1 accumulators -> smem -> wg0 adds and writes epilogue.
__device__ __forceinline__ void mma8(float* c, const unsigned* a, const unsigned* b) {
    asm volatile(
        "mma.sync.aligned.m16n8k8.row.col.f32.tf32.tf32.f32 "
        "{%0,%1,%2,%3}, {%4,%5,%6,%7}, {%8,%9}, {%0,%1,%2,%3};"
        : "+f"(c[0]), "+f"(c[1]), "+f"(c[2]), "+f"(c[3])
        : "r"(a[0]), "r"(a[1]), "r"(a[2]), "r"(a[3]), "r"(b[0]), "r"(b[1]));
}

#define SMWG 2432              // floats per warpgroup buffer (32 * 76)
#define SA(p, w, k, i) (p)[(w) * SMWG + (k) * 76 + (i)]

__global__ __launch_bounds__(256) void mma_gemm(const float* __restrict__ ndb) {
    extern __shared__ __align__(16) float sm[];
    float* sAh = sm;                       // [2][32][76]
    float* sAl = sm + 2 * SMWG;
    float* sBh = sm + 4 * SMWG;
    float* sBl = sm + 6 * SMWG;            // total 8*2432 = 19456 floats = 77824 B

    int z = blockIdx.z;
    float* Cp = (z == 0) ? g_Hn : (z == 1) ? g_A : g_Bm;
    const float* Whz = g_Whi + (size_t)z * HH * HH;
    const float* Wlz = g_Wlo + (size_t)z * HH * HH;

    int bm = blockIdx.x * 64, bn = blockIdx.y * 64;
    int tid = threadIdx.x;
    int wg = tid >> 7;                     // warpgroup 0/1
    int t = tid & 127;
    int warp = t >> 5, lane = t & 31;
    int warpM = warp >> 1, warpN = warp & 1;
    int g = lane >> 2, tg = lane & 3;

    // loader indices (within warpgroup)
    int acol4 = t & 7;
    int arb   = t >> 3;
    int bkr   = t >> 4;
    int bn4   = t & 15;

    float acc[2][4][4];
    #pragma unroll
    for (int mt = 0; mt < 2; mt++)
        #pragma unroll
        for (int nt = 0; nt < 4; nt++)
            #pragma unroll
            for (int r = 0; r < 4; r++) acc[mt][nt][r] = 0.f;

    for (int kt = wg; kt < HH / 32; kt += 2) {
        int k0 = kt * 32;
        // load A tile (64 x 32) hi+lo into this warpgroup's buffers
        #pragma unroll
        for (int rr = 0; rr < 4; rr++) {
            int r = arb + rr * 16;
            float4 vh = *(const float4*)&g_Xhi[(size_t)(bm + r) * HH + k0 + acol4 * 4];
            float4 vl = *(const float4*)&g_Xlo[(size_t)(bm + r) * HH + k0 + acol4 * 4];
            SA(sAh, wg, acol4 * 4 + 0, r) = vh.x; SA(sAh, wg, acol4 * 4 + 1, r) = vh.y;
            SA(sAh, wg, acol4 * 4 + 2, r) = vh.z; SA(sAh, wg, acol4 * 4 + 3, r) = vh.w;
            SA(sAl, wg, acol4 * 4 + 0, r) = vl.x; SA(sAl, wg, acol4 * 4 + 1, r) = vl.y;
            SA(sAl, wg, acol4 * 4 + 2, r) = vl.z; SA(sAl, wg, acol4 * 4 + 3, r) = vl.w;
        }
        // load B tile (32 x 64) hi+lo
        #pragma unroll
        for (int kk = 0; kk < 4; kk++) {
            int k = bkr + kk * 8;
            float4 vh = *(const float4*)&Whz[(size_t)(k0 + k) * HH + bn + bn4 * 4];
            float4 vl = *(const float4*)&Wlz[(size_t)(k0 + k) * HH + bn + bn4 * 4];
            *(float4*)&SA(sBh, wg, k, bn4 * 4) = vh;
            *(float4*)&SA(sBl, wg, k, bn4 * 4) = vl;
        }
        asm volatile("bar.sync %0, %1;" :: "r"(wg + 1), "r"(128) : "memory");

        #pragma unroll
        for (int ks = 0; ks < 4; ks++) {
            int kk = ks * 8;
            unsigned ah[2][4], al[2][4], bh[4][2], bl[4][2];
            #pragma unroll
            for (int mt = 0; mt < 2; mt++) {
                int mb = warpM * 32 + mt * 16;
                ah[mt][0] = __float_as_uint(SA(sAh, wg, kk + tg,     mb + g));
                ah[mt][1] = __float_as_uint(SA(sAh, wg, kk + tg,     mb + g + 8));
                ah[mt][2] = __float_as_uint(SA(sAh, wg, kk + tg + 4, mb + g));
                ah[mt][3] = __float_as_uint(SA(sAh, wg, kk + tg + 4, mb + g + 8));
                al[mt][0] = __float_as_uint(SA(sAl, wg, kk + tg,     mb + g));
                al[mt][1] = __float_as_uint(SA(sAl, wg, kk + tg,     mb + g + 8));
                al[mt][2] = __float_as_uint(SA(sAl, wg, kk + tg + 4, mb + g));
                al[mt][3] = __float_as_uint(SA(sAl, wg, kk + tg + 4, mb + g + 8));
            }
            #pragma unroll
            for (int nt = 0; nt < 4; nt++) {
                int nb = warpN * 32 + nt * 8;
                bh[nt][0] = __float_as_uint(SA(sBh, wg, kk + tg,     nb + g));
                bh[nt][1] = __float_as_uint(SA(sBh, wg, kk + tg + 4, nb + g));
                bl[nt][0] = __float_as_uint(SA(sBl, wg, kk + tg,     nb + g));
                bl[nt][1] = __float_as_uint(SA(sBl, wg, kk + tg + 4, nb + g));
            }
            #pragma unroll
            for (int mt = 0; mt < 2; mt++)
                #pragma unroll
                for (int nt = 0; nt < 4; nt++) {
                    mma8(acc[mt][nt], ah[mt], bh[nt]);
                    mma8(acc[mt][nt], al[mt], bh[nt]);
                    mma8(acc[mt][nt], ah[mt], bl[nt]);
                }
        }
        asm volatile("bar.sync %0, %1;" :: "r"(wg + 1), "r"(128) : "memory");
    }

    // ---- combine warpgroup partial sums via smem (reuse sAh region) ----
    __syncthreads();
    float* sC = sm;                        // 64 x 66 floats = 16896 B (fits)
    if (wg == 1) {
        #pragma unroll
        for (int mt = 0; mt < 2; mt++)
            #pragma unroll
            for (int half = 0; half < 2; half++) {
                int ml = warpM * 32 + mt * 16 + g + half * 8;
                #pragma unroll
                for (int nt = 0; nt < 4; nt++) {
                    int nl = warpN * 32 + nt * 8 + tg * 2;
                    *(float2*)&sC[ml * 66 + nl] =
                        make_float2(acc[mt][nt][half * 2], acc[mt][nt][half * 2 + 1]);
                }
            }
    }
    __syncthreads();
    if (wg == 0) {
        #pragma unroll
        for (int mt = 0; mt < 2; mt++)
            #pragma unroll
            for (int half = 0; half < 2; half++) {
                int ml = warpM * 32 + mt * 16 + g + half * 8;
                int m = bm + ml;
                #pragma unroll
                for (int nt = 0; nt < 4; nt++) {
                    int nl = warpN * 32 + nt * 8 + tg * 2;
                    int n = bn + nl;
                    float2 p = *(const float2*)&sC[ml * 66 + nl];
                    float v0 = acc[mt][nt][half * 2]     + p.x;
                    float v1 = acc[mt][nt][half * 2 + 1] + p.y;
                    if (z == 0) {
                        v0 = tanhf(v0 + ndb[n]);
                        v1 = tanhf(v1 + ndb[n + 1]);
                    }
                    *(float2*)&Cp[(size_t)m * HH + n] = make_float2(v0, v1);
                }
            }
    }
}

// ---------------- 4) tail: node+cls logits, then edges ----------------
__global__ __launch_bounds__(256) void tail_kernel(
        const float* __restrict__ noW, const float* __restrict__ nob,
        const float* __restrict__ coW, const float* __restrict__ cob,
        const float* __restrict__ eb,
        const float* __restrict__ eoW, const float* __restrict__ eob,
        float* __restrict__ out) {
    __shared__ __align__(16) float s_B[HH];
    __shared__ __align__(16) float s_eb[HH];
    __shared__ __align__(16) float s_w0[HH];
    __shared__ __align__(16) float s_w1[HH];
    __shared__ float sred[16];
    int blk = blockIdx.x;
    int tid = threadIdx.x;
    int lane = tid & 31, wid = tid >> 5;

    if (blk < 528) {
        const float* src;
        const float* Wv;
        const float* bv;
        float* dst;
        if (blk < MROWS) {
            src = g_Hn + (size_t)blk * HH; Wv = noW; bv = nob; dst = out + 32 + blk * 2;
        } else {
            int b = blk - MROWS;
            src = g_ch + (size_t)b * HH;  Wv = coW; bv = cob; dst = out + b * 2;
        }
        float p0 = 0.f, p1 = 0.f;
        for (int h = tid; h < HH; h += 256) {
            float v = src[h];
            p0 = fmaf(v, Wv[h * 2],     p0);
            p1 = fmaf(v, Wv[h * 2 + 1], p1);
        }
        #pragma unroll
        for (int o = 16; o > 0; o >>= 1) {
            p0 += __shfl_down_sync(0xffffffffu, p0, o);
            p1 += __shfl_down_sync(0xffffffffu, p1, o);
        }
        if (lane == 0) { sred[wid * 2] = p0; sred[wid * 2 + 1] = p1; }
        __syncthreads();
        if (tid == 0) {
            float a0 = 0.f, a1 = 0.f;
            for (int w = 0; w < 8; w++) { a0 += sred[w * 2]; a1 += sred[w * 2 + 1]; }
            dst[0] = a0 + bv[0]; dst[1] = a1 + bv[1];
        }
        return;
    }

    int eidx = blk - 528;
    int b = eidx / (KSLOT + 1);
    int i = eidx - b * (KSLOT + 1);
    int m = g_m[b];
    float* outp = out + 32 + MROWS * 2;

    for (int h = tid; h < HH; h += 256) {
        s_eb[h] = eb[h];
        s_w0[h] = eoW[h * 2];
        s_w1[h] = eoW[h * 2 + 1];
    }
    if (i < KSLOT && i < m) {
        for (int h = tid; h < HH; h += 256)
            s_B[h] = g_Bm[((size_t)(b * KSLOT + i)) * HH + h];
    }
    __syncthreads();

    if (i < KSLOT) {
        if (i >= m) return;
        for (int j = wid; j < m; j += 8) {
            const float4* Aj = (const float4*)(g_A + ((size_t)(b * KSLOT + j)) * HH);
            float p0 = 0.f, p1 = 0.f;
            #pragma unroll
            for (int it = 0; it < 8; it++) {
                int h4 = it * 32 + lane;
                float4 a  = Aj[h4];
                float4 bv = *(const float4*)&s_B[h4 * 4];
                float4 ev = *(const float4*)&s_eb[h4 * 4];
                float4 w0 = *(const float4*)&s_w0[h4 * 4];
                float4 w1 = *(const float4*)&s_w1[h4 * 4];
                float v0 = tanh_fast(a.x + bv.x + ev.x);
                float v1 = tanh_fast(a.y + bv.y + ev.y);
                float v2 = tanh_fast(a.z + bv.z + ev.z);
                float v3 = tanh_fast(a.w + bv.w + ev.w);
                p0 = fmaf(v0, w0.x, fmaf(v1, w0.y, fmaf(v2, w0.z, fmaf(v3, w0.w, p0))));
                p1 = fmaf(v0, w1.x, fmaf(v1, w1.y, fmaf(v2, w1.z, fmaf(v3, w1.w, p1))));
            }
            #pragma unroll
            for (int o = 16; o > 0; o >>= 1) {
                p0 += __shfl_down_sync(0xffffffffu, p0, o);
                p1 += __shfl_down_sync(0xffffffffu, p1, o);
            }
            if (lane == 0) {
                int e = i * m + j;
                outp[((size_t)b * EE + e) * 2]     = p0 + eob[0];
                outp[((size_t)b * EE + e) * 2 + 1] = p1 + eob[1];
            }
        }
    } else {
        float p0 = 0.f, p1 = 0.f;
        for (int h = tid; h < HH; h += 256) {
            float v = tanhf(s_eb[h]);
            p0 = fmaf(v, s_w0[h], p0);
            p1 = fmaf(v, s_w1[h], p1);
        }
        #pragma unroll
        for (int o = 16; o > 0; o >>= 1) {
            p0 += __shfl_down_sync(0xffffffffu, p0, o);
            p1 += __shfl_down_sync(0xffffffffu, p1, o);
        }
        if (lane == 0) { sred[wid * 2] = p0; sred[wid * 2 + 1] = p1; }
        __syncthreads();
        if (tid == 0) {
            float a0 = 0.f, a1 = 0.f;
            for (int w = 0; w < 8; w++) { a0 += sred[w * 2]; a1 += sred[w * 2 + 1]; }
            sred[0] = a0 + eob[0]; sred[1] = a1 + eob[1];
        }
        __syncthreads();
        float c0 = sred[0], c1 = sred[1];
        for (int e = m * m + tid; e < EE; e += 256) {
            outp[((size_t)b * EE + e) * 2]     = c0;
            outp[((size_t)b * EE + e) * 2 + 1] = c1;
        }
    }
}

// ---------------- launch ----------------
extern "C" void kernel_launch(void* const* d_in, const int* in_sizes, int n_in,
                              void* d_out, int out_size) {
    const float* seq  = (const float*)d_in[0];
    const int*   off  = (const int*)  d_in[1];
    const float* nafW = (const float*)d_in[2];
    const float* nafb = (const float*)d_in[3];
    const float* cdW  = (const float*)d_in[4];
    const float* cdb  = (const float*)d_in[5];
    const float* coW  = (const float*)d_in[6];
    const float* cob  = (const float*)d_in[7];
    const float* ndW  = (const float*)d_in[8];
    const float* ndb  = (const float*)d_in[9];
    const float* noW  = (const float*)d_in[10];
    const float* nob  = (const float*)d_in[11];
    const float* edW  = (const float*)d_in[12];
    const float* edb  = (const float*)d_in[13];
    const float* eoW  = (const float*)d_in[14];
    const float* eob  = (const float*)d_in[15];
    float* out = (float*)d_out;

    const int gemm_smem = 8 * SMWG * (int)sizeof(float);   // 77824 B
    cudaFuncSetAttribute(mma_gemm, cudaFuncAttributeMaxDynamicSharedMemorySize, gemm_smem);

    prep_fused<<<4160, 256>>>(edW, ndW, seq, nafW, nafb, cdW, cdb);
    nodes_kernel<<<dim3(BB, KSLOT), 128>>>(seq, off);
    mma_gemm<<<dim3(512 / 64, HH / 64, 3), 256, gemm_smem>>>(ndb);
    tail_kernel<<<528 + BB * (KSLOT + 1), 256>>>(noW, nob, coW, cob, edb, eoW, eob, out);
}